// round 15
// baseline (speedup 1.0000x reference)
#include <cuda_runtime.h>
#include <math.h>

// Problem constants
#define NN 20000
#define EE 200000
#define BBATCH 16
#define ND 64
#define ED 32
#define GD 32
#define HD 128
#define DOF 6
#define PI_F 3.14159265358979f

typedef unsigned long long ull;

// ---------------------------------------------------------------------------
// Scratch (static __device__ arrays; no allocation allowed)
// ---------------------------------------------------------------------------
__device__ float g_AB[(size_t)NN * 256];     // per-node A (x@W1a) [0:128], B (x@W1b) [128:256]
__device__ float g_accum[(size_t)NN * HD];   // segment sums
__device__ float g_cnt[NN];                  // segment counts

// ---- packed f32x2 helpers ----
#define PACK2(d, s)      asm("mov.b64 %0, {%1, %1};" : "=l"(d) : "f"(s))
#define UNPK2(lo, hi, v) asm("mov.b64 {%0, %1}, %2;" : "=f"(lo), "=f"(hi) : "l"(v))
#define FMA2(acc, a, b)  asm("fma.rn.f32x2 %0, %1, %2, %0;" : "+l"(acc) : "l"(a), "l"(b))
#define ADD2(d, a, b)    asm("add.rn.f32x2 %0, %1, %2;" : "=l"(d) : "l"(a), "l"(b))

__device__ __forceinline__ float4 relu4(float4 v) {
    v.x = fmaxf(v.x, 0.f); v.y = fmaxf(v.y, 0.f);
    v.z = fmaxf(v.z, 0.f); v.w = fmaxf(v.w, 0.f);
    return v;
}

__device__ __forceinline__ void red_add_v4(float* p, float4 v) {
    asm volatile("red.global.add.v4.f32 [%0], {%1,%2,%3,%4};"
                 :: "l"(p), "f"(v.x), "f"(v.y), "f"(v.z), "f"(v.w) : "memory");
}

// ---------------------------------------------------------------------------
// Kernel 1: per-node A = x@W1[0:64], B = x@W1[64:128]; zero accum/cnt
// block = 256 threads, tile = 32 nodes, 3 blocks/SM (W1 streamed from global,
// lockstep-reused through L1/L2); smem = X tile only (8.7KB)
// ---------------------------------------------------------------------------
#define PRE_SMEM (32 * 68 * 4)

__global__ void __launch_bounds__(256, 3)
k_pre(const float* __restrict__ xfeat, const float* __restrict__ W1) {
    extern __shared__ float sm[];
    float* sX = sm;  // 32*68 (padded)

    const int warp = threadIdx.x >> 5, lane = threadIdx.x & 31;
    const int NT = NN / 32;   // 625

    for (int tile = blockIdx.x; tile < NT; tile += gridDim.x) {
        const int nb = tile * 32;
        __syncthreads();
        for (int idx = threadIdx.x; idx < 32 * 16; idx += 256) {
            int n = idx >> 4, k4 = idx & 15;
            ((float4*)(sX + n * 68))[k4] =
                ((const float4*)(xfeat + (size_t)(nb + n) * 64))[k4];
        }
        __syncthreads();

        ull accA[4][2], accB[4][2];
#pragma unroll
        for (int r = 0; r < 4; r++) {
            accA[r][0] = 0ull; accA[r][1] = 0ull;
            accB[r][0] = 0ull; accB[r][1] = 0ull;
        }
#pragma unroll 4
        for (int k = 0; k < 64; k++) {
            ulonglong2 wa = *(const ulonglong2*)(W1 + (size_t)k * 128 + 4 * lane);
            ulonglong2 wb = *(const ulonglong2*)(W1 + (size_t)(64 + k) * 128 + 4 * lane);
#pragma unroll
            for (int r = 0; r < 4; r++) {
                float x = sX[(4 * warp + r) * 68 + k];
                ull xx; PACK2(xx, x);
                FMA2(accA[r][0], xx, wa.x); FMA2(accA[r][1], xx, wa.y);
                FMA2(accB[r][0], xx, wb.x); FMA2(accB[r][1], xx, wb.y);
            }
        }
#pragma unroll
        for (int r = 0; r < 4; r++) {
            int gn = nb + 4 * warp + r;
            float4 oa, ob;
            UNPK2(oa.x, oa.y, accA[r][0]); UNPK2(oa.z, oa.w, accA[r][1]);
            UNPK2(ob.x, ob.y, accB[r][0]); UNPK2(ob.z, ob.w, accB[r][1]);
            ((float4*)(g_AB + (size_t)gn * 256))[lane] = oa;
            ((float4*)(g_AB + (size_t)gn * 256 + 128))[lane] = ob;
            ((float4*)(g_accum + (size_t)gn * 128))[lane] = make_float4(0.f, 0.f, 0.f, 0.f);
            if (lane == 0) g_cnt[gn] = 0.f;
        }
    }
}

// ---------------------------------------------------------------------------
// Kernel 2: fused edge MLP + atomic scatter
// block = 512 threads (16 warps), tile = 64 edges -> 128 rows, 2 blocks/SM
// (32 warps/SM). W2 streamed from global (lockstep L1/L2 reuse). Phase 4 in
// two 4-row passes to fit the 64-reg budget without inner-loop spills.
// ---------------------------------------------------------------------------
// smem float offsets
#define EO_H1  0       // 128*132 = 16896
#define EO_W1E 16896   // 32*128 = 4096
#define EO_W1P 20992   // 12*128 = 1536
#define EO_B1  22528   // 128
#define EO_B2  22656   // 128
#define EO_EF  22784   // 64*32 = 2048
#define EO_P   24832   // 128*12 = 1536
#define EO_TGT 26368   // 128 ints
#define EDGE_SMEM ((26368 + 128) * 4)   // 105,984 B  (x2 = 212KB <= 228KB/SM)

__global__ void __launch_bounds__(512, 2)
k_edge(const float* __restrict__ T_R, const float* __restrict__ T_t,
       const float* __restrict__ edge_feat,
       const float* __restrict__ Tij_R, const float* __restrict__ Tij_t,
       const int* __restrict__ edge_index,
       const float* __restrict__ W1, const float* __restrict__ b1,
       const float* __restrict__ W2, const float* __restrict__ b2) {
    extern __shared__ float sm[];
    float* sH1  = sm + EO_H1;
    float* sW1e = sm + EO_W1E;
    float* sW1p = sm + EO_W1P;
    float* sb1  = sm + EO_B1;
    float* sb2  = sm + EO_B2;
    float* sEF  = sm + EO_EF;
    float* sP   = sm + EO_P;
    int*   sTgt = (int*)(sm + EO_TGT);

    const int tid = threadIdx.x;
    for (int idx = tid; idx < 4096 / 4; idx += 512)
        ((float4*)sW1e)[idx] = ((const float4*)(W1 + 128 * 128))[idx];
    for (int idx = tid; idx < 1536 / 4; idx += 512)
        ((float4*)sW1p)[idx] = ((const float4*)(W1 + 160 * 128))[idx];
    if (tid < 128) { sb1[tid] = b1[tid]; sb2[tid] = b2[tid]; }
    __syncthreads();

    const int warp = tid >> 5, lane = tid & 31;
    const ulonglong2 b1p = *(const ulonglong2*)(sb1 + 4 * lane);
    const ulonglong2 b2p = *(const ulonglong2*)(sb2 + 4 * lane);

    for (int tile = blockIdx.x; tile < EE / 64; tile += gridDim.x) {
        const int eb = tile * 64;
        __syncthreads();   // previous tile fully consumed

        // edge_feat tile: 64 edges * 32 floats = 512 float4s (one per thread)
        ((float4*)sEF)[tid] = ((const float4*)(edge_feat + (size_t)eb * 32))[tid];

        // pose vectors: one thread per edge
        if (tid < 64) {
            const int e = tid, ge = eb + e;
            const int gi = edge_index[ge];
            const int gj = edge_index[EE + ge];
            sTgt[2 * e]     = gj;   // f_ij aggregates into j
            sTgt[2 * e + 1] = gi;   // f_ji aggregates into i

            float Ri[9], Rj[9], TRm[9], ti[3], tj[3], Tt[3];
#pragma unroll
            for (int k = 0; k < 9; k++) {
                Ri[k]  = T_R[(size_t)gi * 9 + k];
                Rj[k]  = T_R[(size_t)gj * 9 + k];
                TRm[k] = Tij_R[(size_t)ge * 9 + k];
            }
#pragma unroll
            for (int k = 0; k < 3; k++) {
                ti[k] = T_t[(size_t)gi * 3 + k];
                tj[k] = T_t[(size_t)gj * 3 + k];
                Tt[k] = Tij_t[(size_t)ge * 3 + k];
            }
            // Ra = Rj * Ri^T ; ta = tj - Ra*ti
            float Ra[9], ta[3];
#pragma unroll
            for (int r = 0; r < 3; r++) {
#pragma unroll
                for (int c = 0; c < 3; c++)
                    Ra[r * 3 + c] = Rj[r * 3 + 0] * Ri[c * 3 + 0]
                                  + Rj[r * 3 + 1] * Ri[c * 3 + 1]
                                  + Rj[r * 3 + 2] * Ri[c * 3 + 2];
                ta[r] = tj[r] - (Ra[r * 3 + 0] * ti[0] + Ra[r * 3 + 1] * ti[1]
                               + Ra[r * 3 + 2] * ti[2]);
            }
            // e_ij = (Ra, ta) * inv(Tij): R = Ra*TR^T, t = ta - R*Tt
            {
                float* pv = sP + (2 * e) * 12;
#pragma unroll
                for (int r = 0; r < 3; r++) {
                    float re[3];
#pragma unroll
                    for (int c = 0; c < 3; c++)
                        re[c] = Ra[r * 3 + 0] * TRm[c * 3 + 0]
                              + Ra[r * 3 + 1] * TRm[c * 3 + 1]
                              + Ra[r * 3 + 2] * TRm[c * 3 + 2];
                    float te = ta[r] - (re[0] * Tt[0] + re[1] * Tt[1] + re[2] * Tt[2]);
                    pv[4 * r + 0] = re[0]; pv[4 * r + 1] = re[1];
                    pv[4 * r + 2] = re[2]; pv[4 * r + 3] = te;
                }
            }
            // e_ji: Rb = Ra^T, tb = ti - Rb*tj; R = Rb*TR, t = Rb*Tt + tb
            {
                float* pv = sP + (2 * e + 1) * 12;
#pragma unroll
                for (int r = 0; r < 3; r++) {
                    float bv0 = Ra[0 * 3 + r], bv1 = Ra[1 * 3 + r], bv2 = Ra[2 * 3 + r];
                    float tb = ti[r] - (bv0 * tj[0] + bv1 * tj[1] + bv2 * tj[2]);
                    float re[3];
#pragma unroll
                    for (int c = 0; c < 3; c++)
                        re[c] = bv0 * TRm[0 * 3 + c] + bv1 * TRm[1 * 3 + c] + bv2 * TRm[2 * 3 + c];
                    float te = bv0 * Tt[0] + bv1 * Tt[1] + bv2 * Tt[2] + tb;
                    pv[4 * r + 0] = re[0]; pv[4 * r + 1] = re[1];
                    pv[4 * r + 2] = re[2]; pv[4 * r + 3] = te;
                }
            }
        }
        __syncthreads();

        // -------- phase 3: H1 (layer 1 + relu), warp = edge-group -----------
#pragma unroll
        for (int m = 0; m < 4; m++) {
            const int e = warp + 16 * m;
            const int gi = sTgt[2 * e + 1], gj = sTgt[2 * e];
            const ulonglong2 Ai = ((const ulonglong2*)(g_AB + (size_t)gi * 256))[lane];
            const ulonglong2 Bj = ((const ulonglong2*)(g_AB + (size_t)gj * 256 + 128))[lane];
            const ulonglong2 Aj = ((const ulonglong2*)(g_AB + (size_t)gj * 256))[lane];
            const ulonglong2 Bi = ((const ulonglong2*)(g_AB + (size_t)gi * 256 + 128))[lane];

            ull et0 = 0ull, et1 = 0ull;
            const float* efr = sEF + e * 32;
#pragma unroll 8
            for (int k = 0; k < 32; k++) {
                ulonglong2 w = *(const ulonglong2*)(sW1e + k * 128 + 4 * lane);
                ull e2; PACK2(e2, efr[k]);
                FMA2(et0, e2, w.x); FMA2(et1, e2, w.y);
            }
            ull q0 = 0ull, q1 = 0ull, p0 = 0ull, p1 = 0ull;
            const float* pr = sP + (2 * e) * 12;
#pragma unroll
            for (int k = 0; k < 12; k++) {
                ulonglong2 w = *(const ulonglong2*)(sW1p + k * 128 + 4 * lane);
                ull a2; PACK2(a2, pr[k]);
                ull c2; PACK2(c2, pr[12 + k]);
                FMA2(q0, a2, w.x); FMA2(q1, a2, w.y);
                FMA2(p0, c2, w.x); FMA2(p1, c2, w.y);
            }
            ull s0, s1, t0, t1;
            ADD2(s0, Ai.x, Bj.x); ADD2(s0, s0, et0); ADD2(s0, s0, q0); ADD2(s0, s0, b1p.x);
            ADD2(s1, Ai.y, Bj.y); ADD2(s1, s1, et1); ADD2(s1, s1, q1); ADD2(s1, s1, b1p.y);
            ADD2(t0, Aj.x, Bi.x); ADD2(t0, t0, et0); ADD2(t0, t0, p0); ADD2(t0, t0, b1p.x);
            ADD2(t1, Aj.y, Bi.y); ADD2(t1, t1, et1); ADD2(t1, t1, p1); ADD2(t1, t1, b1p.y);
            float4 hij, hji;
            UNPK2(hij.x, hij.y, s0); UNPK2(hij.z, hij.w, s1);
            UNPK2(hji.x, hji.y, t0); UNPK2(hji.z, hji.w, t1);
            ((float4*)(sH1 + (size_t)(2 * e) * 132))[lane]     = relu4(hij);
            ((float4*)(sH1 + (size_t)(2 * e + 1) * 132))[lane] = relu4(hji);
        }
        __syncthreads();

        // -------- phase 4: layer 2 GEMM + scatter, two 4-row passes ---------
        // W2 streamed from global: warps advance through k in lockstep, so
        // each W2 row is fetched from L2 once per tile and L1-reused.
#pragma unroll
        for (int pass = 0; pass < 2; pass++) {
            ull acc[4][2];
#pragma unroll
            for (int r = 0; r < 4; r++) { acc[r][0] = b2p.x; acc[r][1] = b2p.y; }
            const float* hb = sH1 + (size_t)(8 * warp + 4 * pass) * 132;
#pragma unroll 2
            for (int k = 0; k < 128; k += 4) {
                ulonglong2 w0 = *(const ulonglong2*)(W2 + (size_t)(k + 0) * 128 + 4 * lane);
                ulonglong2 w1 = *(const ulonglong2*)(W2 + (size_t)(k + 1) * 128 + 4 * lane);
                ulonglong2 w2 = *(const ulonglong2*)(W2 + (size_t)(k + 2) * 128 + 4 * lane);
                ulonglong2 w3 = *(const ulonglong2*)(W2 + (size_t)(k + 3) * 128 + 4 * lane);
#pragma unroll
                for (int r = 0; r < 4; r++) {
                    float4 h4 = *(const float4*)(hb + r * 132 + k);  // broadcast
                    ull h0; PACK2(h0, h4.x);
                    FMA2(acc[r][0], h0, w0.x); FMA2(acc[r][1], h0, w0.y);
                    ull h1; PACK2(h1, h4.y);
                    FMA2(acc[r][0], h1, w1.x); FMA2(acc[r][1], h1, w1.y);
                    ull h2; PACK2(h2, h4.z);
                    FMA2(acc[r][0], h2, w2.x); FMA2(acc[r][1], h2, w2.y);
                    ull h3; PACK2(h3, h4.w);
                    FMA2(acc[r][0], h3, w3.x); FMA2(acc[r][1], h3, w3.y);
                }
            }
#pragma unroll
            for (int r = 0; r < 4; r++) {
                const int row = 8 * warp + 4 * pass + r;
                const int tgt = sTgt[row];
                float4 o;
                UNPK2(o.x, o.y, acc[r][0]); UNPK2(o.z, o.w, acc[r][1]);
                red_add_v4(g_accum + (size_t)tgt * 128 + 4 * lane, relu4(o));
                if (lane == 0) atomicAdd(&g_cnt[tgt], 1.0f);
            }
        }
    }
}

// ---------------------------------------------------------------------------
// Kernel 3: node MLP (224->128->70) + SE3 epilogue
// block = 256 threads, tile = 32 nodes, 2 blocks/SM; W3 from GLOBAL
// ---------------------------------------------------------------------------
#define NO_W4  0       // 128*96 = 12288 (cols padded 70->96 with zeros)
#define NO_B3  12288   // 128
#define NO_B4  12416   // 128 (96 used)
#define NO_U   12544   // 16*32 = 512
#define NO_G   13056   // 32*228 = 7296
#define NO_H3  20352   // 32*132 = 4224
#define NO_OUT 24576   // 32*72  = 2304
#define NODE_SMEM ((24576 + 2304) * 4)   // 107,520 B

__global__ void __launch_bounds__(256, 2)
k_node(const float* __restrict__ xfeat, const float* __restrict__ T_R,
       const float* __restrict__ T_t, const float* __restrict__ u,
       const int* __restrict__ batch,
       const float* __restrict__ W3, const float* __restrict__ b3,
       const float* __restrict__ W4, const float* __restrict__ b4,
       float* __restrict__ out) {
    extern __shared__ float sm[];
    float* sW4 = sm + NO_W4;
    float* sb3 = sm + NO_B3;
    float* sb4 = sm + NO_B4;
    float* sU  = sm + NO_U;
    float* sG  = sm + NO_G;    // stride 228
    float* sH3 = sm + NO_H3;   // stride 132
    float* sO  = sm + NO_OUT;  // stride 72

    const int tid = threadIdx.x;
    for (int idx = tid; idx < 128 * 96; idx += 256) {
        int k = idx / 96, c = idx % 96;
        sW4[idx] = (c < 70) ? W4[k * 70 + c] : 0.f;
    }
    if (tid < 128) sb3[tid] = b3[tid];
    if (tid < 96)  sb4[tid] = (tid < 70) ? b4[tid] : 0.f;
    for (int idx = tid; idx < 512; idx += 256) sU[idx] = u[idx];
    __syncthreads();

    const int warp = tid >> 5, lane = tid & 31;
    const ulonglong2 b3p = *(const ulonglong2*)(sb3 + 4 * lane);

    for (int tile = blockIdx.x; tile < NN / 32; tile += gridDim.x) {
        const int nb = tile * 32;
        __syncthreads();

        // build G = [aggr(128) | xfeat(64) | u[batch](32)]
        for (int idx = tid; idx < 1024; idx += 256) {
            int n = idx >> 5, c4 = idx & 31;
            int gn = nb + n;
            float4 s = ((const float4*)(g_accum + (size_t)gn * 128))[c4];
            float inv = 1.f / fmaxf(g_cnt[gn], 1.f);
            s.x *= inv; s.y *= inv; s.z *= inv; s.w *= inv;
            ((float4*)(sG + n * 228))[c4] = s;
        }
        for (int idx = tid; idx < 512; idx += 256) {
            int n = idx >> 4, c4 = idx & 15;
            ((float4*)(sG + n * 228 + 128))[c4] =
                ((const float4*)(xfeat + (size_t)(nb + n) * 64))[c4];
        }
        {
            int n = tid >> 3, c4 = tid & 7;
            int bn = batch[nb + n];
            ((float4*)(sG + n * 228 + 192))[c4] = ((const float4*)(sU + bn * 32))[c4];
        }
        __syncthreads();

        // GEMM1: H3 = relu(G @ W3 + b3); W3 streamed from global
        {
            ull acc[4][2];
#pragma unroll
            for (int r = 0; r < 4; r++) { acc[r][0] = b3p.x; acc[r][1] = b3p.y; }
#pragma unroll 4
            for (int k = 0; k < 224; k++) {
                ulonglong2 w = *(const ulonglong2*)(W3 + (size_t)k * 128 + 4 * lane);
#pragma unroll
                for (int r = 0; r < 4; r++) {
                    ull g2; PACK2(g2, sG[(4 * warp + r) * 228 + k]);
                    FMA2(acc[r][0], g2, w.x); FMA2(acc[r][1], g2, w.y);
                }
            }
#pragma unroll
            for (int r = 0; r < 4; r++) {
                float4 o;
                UNPK2(o.x, o.y, acc[r][0]); UNPK2(o.z, o.w, acc[r][1]);
                ((float4*)(sH3 + (4 * warp + r) * 132))[lane] = relu4(o);
            }
        }
        __syncthreads();

        // GEMM2: OUT = H3 @ W4 + b4 (70 cols, padded to 96)
        {
            float a0[4], a1[4], a2[4];
            float b40 = sb4[lane], b41 = sb4[32 + lane], b42 = sb4[64 + lane];
#pragma unroll
            for (int r = 0; r < 4; r++) { a0[r] = b40; a1[r] = b41; a2[r] = b42; }
#pragma unroll 4
            for (int k = 0; k < 128; k++) {
                const float* wr = sW4 + k * 96;
                float w0 = wr[lane], w1 = wr[32 + lane], w2 = wr[64 + lane];
#pragma unroll
                for (int r = 0; r < 4; r++) {
                    float h = sH3[(4 * warp + r) * 132 + k];
                    a0[r] = fmaf(h, w0, a0[r]);
                    a1[r] = fmaf(h, w1, a1[r]);
                    a2[r] = fmaf(h, w2, a2[r]);
                }
            }
#pragma unroll
            for (int r = 0; r < 4; r++) {
                float* orow = sO + (4 * warp + r) * 72;
                orow[lane] = a0[r];
                orow[32 + lane] = a1[r];
                if (lane < 6) orow[64 + lane] = a2[r];
            }
        }
        __syncthreads();

        // epilogue: xfeat_out = xfeat + xupd
        for (int idx = tid; idx < 2048; idx += 256) {
            int n = idx >> 6, c = idx & 63;
            int gn = nb + n;
            out[(size_t)gn * 77 + c] = xfeat[(size_t)gn * 64 + c] + sO[n * 72 + c];
        }
        // SE3 exp + compose, one thread per node
        if (tid < 32) {
            const int n = tid, gn = nb + n;
            const float* orow = sO + n * 72;
            float rho0 = orow[64], rho1 = orow[65], rho2 = orow[66];
            float p0 = orow[67], p1 = orow[68], p2 = orow[69];
            float th0 = sqrtf(p0 * p0 + p1 * p1 + p2 * p2);
            float s = PI_F * tanhf(th0 / PI_F) / (th0 + 1e-8f);
            p0 *= s; p1 *= s; p2 *= s;
            float th2 = p0 * p0 + p1 * p1 + p2 * p2;
            float th = sqrtf(th2 + 1e-12f);
            float a, b, c;
            if (th < 1e-4f) {
                a = 1.f - th2 / 6.f;
                b = 0.5f - th2 / 24.f;
                c = 1.f / 6.f - th2 / 120.f;
            } else {
                float sth = sinf(th), cth = cosf(th);
                a = sth / th;
                b = (1.f - cth) / th2;
                c = (th - sth) / (th2 * th);
            }
            float R[9], V[9];
            R[0] = 1.f + b * (p0 * p0 - th2); R[1] = -a * p2 + b * p0 * p1; R[2] =  a * p1 + b * p0 * p2;
            R[3] =  a * p2 + b * p1 * p0;    R[4] = 1.f + b * (p1 * p1 - th2); R[5] = -a * p0 + b * p1 * p2;
            R[6] = -a * p1 + b * p2 * p0;    R[7] =  a * p0 + b * p2 * p1; R[8] = 1.f + b * (p2 * p2 - th2);
            V[0] = 1.f + c * (p0 * p0 - th2); V[1] = -b * p2 + c * p0 * p1; V[2] =  b * p1 + c * p0 * p2;
            V[3] =  b * p2 + c * p1 * p0;    V[4] = 1.f + c * (p1 * p1 - th2); V[5] = -b * p0 + c * p1 * p2;
            V[6] = -b * p1 + c * p2 * p0;    V[7] =  b * p0 + c * p2 * p1; V[8] = 1.f + c * (p2 * p2 - th2);
            float td0 = V[0] * rho0 + V[1] * rho1 + V[2] * rho2;
            float td1 = V[3] * rho0 + V[4] * rho1 + V[5] * rho2;
            float td2 = V[6] * rho0 + V[7] * rho1 + V[8] * rho2;

            float TRn[9], Ttn[3];
#pragma unroll
            for (int k = 0; k < 9; k++) TRn[k] = T_R[(size_t)gn * 9 + k];
#pragma unroll
            for (int k = 0; k < 3; k++) Ttn[k] = T_t[(size_t)gn * 3 + k];

            float* op = out + (size_t)gn * 77 + 64;
#pragma unroll
            for (int r = 0; r < 3; r++) {
#pragma unroll
                for (int cc = 0; cc < 3; cc++)
                    op[3 * r + cc] = R[r * 3 + 0] * TRn[0 * 3 + cc]
                                   + R[r * 3 + 1] * TRn[1 * 3 + cc]
                                   + R[r * 3 + 2] * TRn[2 * 3 + cc];
            }
            float tdv[3] = {td0, td1, td2};
#pragma unroll
            for (int r = 0; r < 3; r++)
                op[9 + r] = R[r * 3 + 0] * Ttn[0] + R[r * 3 + 1] * Ttn[1]
                          + R[r * 3 + 2] * Ttn[2] + tdv[r];
            op[12] = sqrtf(th2);
        }
    }
}

// ---------------------------------------------------------------------------
// Host launcher
// ---------------------------------------------------------------------------
extern "C" void kernel_launch(void* const* d_in, const int* in_sizes, int n_in,
                              void* d_out, int out_size) {
    (void)in_sizes; (void)n_in; (void)out_size;
    const float* xfeat     = (const float*)d_in[0];
    const float* T_R       = (const float*)d_in[1];
    const float* T_t       = (const float*)d_in[2];
    const float* edge_feat = (const float*)d_in[3];
    const float* Tij_R     = (const float*)d_in[4];
    const float* Tij_t     = (const float*)d_in[5];
    const float* u         = (const float*)d_in[6];
    const int*   edge_idx  = (const int*)d_in[7];
    const int*   batch     = (const int*)d_in[8];
    const float* W1 = (const float*)d_in[9];
    const float* b1 = (const float*)d_in[10];
    const float* W2 = (const float*)d_in[11];
    const float* b2 = (const float*)d_in[12];
    const float* W3 = (const float*)d_in[13];
    const float* b3 = (const float*)d_in[14];
    const float* W4 = (const float*)d_in[15];
    const float* b4 = (const float*)d_in[16];
    float* out = (float*)d_out;

    cudaFuncSetAttribute(k_pre,  cudaFuncAttributeMaxDynamicSharedMemorySize, PRE_SMEM);
    cudaFuncSetAttribute(k_edge, cudaFuncAttributeMaxDynamicSharedMemorySize, EDGE_SMEM);
    cudaFuncSetAttribute(k_node, cudaFuncAttributeMaxDynamicSharedMemorySize, NODE_SMEM);

    k_pre<<<444, 256, PRE_SMEM>>>(xfeat, W1);
    k_edge<<<296, 512, EDGE_SMEM>>>(T_R, T_t, edge_feat, Tij_R, Tij_t,
                                    edge_idx, W1, b1, W2, b2);
    k_node<<<296, 256, NODE_SMEM>>>(xfeat, T_R, T_t, u, batch,
                                    W3, b3, W4, b4, out);
}

// round 16
// speedup vs baseline: 1.2786x; 1.2786x over previous
#include <cuda_runtime.h>
#include <math.h>

// Problem constants
#define NN 20000
#define EE 200000
#define BBATCH 16
#define ND 64
#define ED 32
#define GD 32
#define HD 128
#define DOF 6
#define PI_F 3.14159265358979f

typedef unsigned long long ull;

// ---------------------------------------------------------------------------
// Scratch (static __device__ arrays; no allocation allowed)
// ---------------------------------------------------------------------------
__device__ float g_AB[(size_t)NN * 256];     // per-node A (x@W1a) [0:128], B (x@W1b) [128:256]
__device__ float g_accum[(size_t)NN * HD];   // segment sums
__device__ float g_cnt[NN];                  // segment counts

// ---- packed f32x2 helpers ----
#define PACK2(d, s)      asm("mov.b64 %0, {%1, %1};" : "=l"(d) : "f"(s))
#define UNPK2(lo, hi, v) asm("mov.b64 {%0, %1}, %2;" : "=f"(lo), "=f"(hi) : "l"(v))
#define FMA2(acc, a, b)  asm("fma.rn.f32x2 %0, %1, %2, %0;" : "+l"(acc) : "l"(a), "l"(b))
#define ADD2(d, a, b)    asm("add.rn.f32x2 %0, %1, %2;" : "=l"(d) : "l"(a), "l"(b))

__device__ __forceinline__ float4 relu4(float4 v) {
    v.x = fmaxf(v.x, 0.f); v.y = fmaxf(v.y, 0.f);
    v.z = fmaxf(v.z, 0.f); v.w = fmaxf(v.w, 0.f);
    return v;
}

__device__ __forceinline__ void red_add_v4(float* p, float4 v) {
    asm volatile("red.global.add.v4.f32 [%0], {%1,%2,%3,%4};"
                 :: "l"(p), "f"(v.x), "f"(v.y), "f"(v.z), "f"(v.w) : "memory");
}

// ---------------------------------------------------------------------------
// Kernel 1: per-node A = x@W1[0:64], B = x@W1[64:128]; zero accum/cnt
// block = 256 threads, tile = 32 nodes, grid = 296 (2 blocks/SM, W1 in smem)
// — the measured-best k_pre configuration (29.3us).
// ---------------------------------------------------------------------------
#define PRE_SMEM ((128 * 128 + 32 * 68) * 4)

__global__ void __launch_bounds__(256, 2)
k_pre(const float* __restrict__ xfeat, const float* __restrict__ W1) {
    extern __shared__ float sm[];
    float* sW = sm;              // 128*128
    float* sX = sm + 128 * 128;  // 32*68 (padded)

    for (int idx = threadIdx.x; idx < (128 * 128) / 4; idx += 256)
        ((float4*)sW)[idx] = ((const float4*)W1)[idx];

    const int warp = threadIdx.x >> 5, lane = threadIdx.x & 31;
    const int NT = NN / 32;   // 625

    for (int tile = blockIdx.x; tile < NT; tile += gridDim.x) {
        const int nb = tile * 32;
        __syncthreads();
        for (int idx = threadIdx.x; idx < 32 * 16; idx += 256) {
            int n = idx >> 4, k4 = idx & 15;
            ((float4*)(sX + n * 68))[k4] =
                ((const float4*)(xfeat + (size_t)(nb + n) * 64))[k4];
        }
        __syncthreads();

        ull accA[4][2], accB[4][2];
#pragma unroll
        for (int r = 0; r < 4; r++) {
            accA[r][0] = 0ull; accA[r][1] = 0ull;
            accB[r][0] = 0ull; accB[r][1] = 0ull;
        }
#pragma unroll 4
        for (int k = 0; k < 64; k++) {
            ulonglong2 wa = *(const ulonglong2*)(sW + k * 128 + 4 * lane);
            ulonglong2 wb = *(const ulonglong2*)(sW + (64 + k) * 128 + 4 * lane);
#pragma unroll
            for (int r = 0; r < 4; r++) {
                float x = sX[(4 * warp + r) * 68 + k];
                ull xx; PACK2(xx, x);
                FMA2(accA[r][0], xx, wa.x); FMA2(accA[r][1], xx, wa.y);
                FMA2(accB[r][0], xx, wb.x); FMA2(accB[r][1], xx, wb.y);
            }
        }
#pragma unroll
        for (int r = 0; r < 4; r++) {
            int gn = nb + 4 * warp + r;
            float4 oa, ob;
            UNPK2(oa.x, oa.y, accA[r][0]); UNPK2(oa.z, oa.w, accA[r][1]);
            UNPK2(ob.x, ob.y, accB[r][0]); UNPK2(ob.z, ob.w, accB[r][1]);
            ((float4*)(g_AB + (size_t)gn * 256))[lane] = oa;
            ((float4*)(g_AB + (size_t)gn * 256 + 128))[lane] = ob;
            ((float4*)(g_accum + (size_t)gn * 128))[lane] = make_float4(0.f, 0.f, 0.f, 0.f);
            if (lane == 0) g_cnt[gn] = 0.f;
        }
    }
}

// ---------------------------------------------------------------------------
// Kernel 2: fused edge MLP (layer1 factorized + layer2 GEMM) + atomic scatter
// block = 640 threads (20 warps = 5/SMSP), tile = 80 edges -> 160 rows,
// 1 block/SM (smem 192KB). Weights in smem (proven); +25% warps vs 573us
// config at identical per-row cost.
// ---------------------------------------------------------------------------
// smem float offsets
#define EO_W2  0       // 128*128 = 16384
#define EO_W1E 16384   // 32*128  = 4096
#define EO_W1P 20480   // 12*128  = 1536
#define EO_B1  22016   // 128
#define EO_B2  22144   // 128
#define EO_EF  22272   // 80*32   = 2560
#define EO_P   24832   // 160*12  = 1920
#define EO_H1  26752   // 160*132 = 21120
#define EO_TGT 47872   // 160 ints
#define EDGE_SMEM ((47872 + 160) * 4)   // 192,128 B

__global__ void __launch_bounds__(640, 1)
k_edge(const float* __restrict__ T_R, const float* __restrict__ T_t,
       const float* __restrict__ edge_feat,
       const float* __restrict__ Tij_R, const float* __restrict__ Tij_t,
       const int* __restrict__ edge_index,
       const float* __restrict__ W1, const float* __restrict__ b1,
       const float* __restrict__ W2, const float* __restrict__ b2) {
    extern __shared__ float sm[];
    float* sW2  = sm + EO_W2;
    float* sW1e = sm + EO_W1E;
    float* sW1p = sm + EO_W1P;
    float* sb1  = sm + EO_B1;
    float* sb2  = sm + EO_B2;
    float* sEF  = sm + EO_EF;
    float* sP   = sm + EO_P;
    float* sH1  = sm + EO_H1;
    int*   sTgt = (int*)(sm + EO_TGT);

    const int tid = threadIdx.x;
    for (int idx = tid; idx < 16384 / 4; idx += 640)
        ((float4*)sW2)[idx] = ((const float4*)W2)[idx];
    for (int idx = tid; idx < 4096 / 4; idx += 640)
        ((float4*)sW1e)[idx] = ((const float4*)(W1 + 128 * 128))[idx];
    for (int idx = tid; idx < 1536 / 4; idx += 640)
        ((float4*)sW1p)[idx] = ((const float4*)(W1 + 160 * 128))[idx];
    if (tid < 128) { sb1[tid] = b1[tid]; sb2[tid] = b2[tid]; }
    __syncthreads();

    const int warp = tid >> 5, lane = tid & 31;
    const ulonglong2 b1p = *(const ulonglong2*)(sb1 + 4 * lane);
    const ulonglong2 b2p = *(const ulonglong2*)(sb2 + 4 * lane);

    const int NT = EE / 80;   // 2500 tiles
    for (int tile = blockIdx.x; tile < NT; tile += gridDim.x) {
        const int eb = tile * 80;
        __syncthreads();   // previous tile fully consumed

        // edge_feat tile: 80 edges * 32 floats = 640 float4s (one per thread)
        ((float4*)sEF)[tid] = ((const float4*)(edge_feat + (size_t)eb * 32))[tid];

        // pose vectors: one thread per edge
        if (tid < 80) {
            const int e = tid, ge = eb + e;
            const int gi = edge_index[ge];
            const int gj = edge_index[EE + ge];
            sTgt[2 * e]     = gj;   // f_ij aggregates into j
            sTgt[2 * e + 1] = gi;   // f_ji aggregates into i

            float Ri[9], Rj[9], TRm[9], ti[3], tj[3], Tt[3];
#pragma unroll
            for (int k = 0; k < 9; k++) {
                Ri[k]  = T_R[(size_t)gi * 9 + k];
                Rj[k]  = T_R[(size_t)gj * 9 + k];
                TRm[k] = Tij_R[(size_t)ge * 9 + k];
            }
#pragma unroll
            for (int k = 0; k < 3; k++) {
                ti[k] = T_t[(size_t)gi * 3 + k];
                tj[k] = T_t[(size_t)gj * 3 + k];
                Tt[k] = Tij_t[(size_t)ge * 3 + k];
            }
            // Ra = Rj * Ri^T ; ta = tj - Ra*ti
            float Ra[9], ta[3];
#pragma unroll
            for (int r = 0; r < 3; r++) {
#pragma unroll
                for (int c = 0; c < 3; c++)
                    Ra[r * 3 + c] = Rj[r * 3 + 0] * Ri[c * 3 + 0]
                                  + Rj[r * 3 + 1] * Ri[c * 3 + 1]
                                  + Rj[r * 3 + 2] * Ri[c * 3 + 2];
                ta[r] = tj[r] - (Ra[r * 3 + 0] * ti[0] + Ra[r * 3 + 1] * ti[1]
                               + Ra[r * 3 + 2] * ti[2]);
            }
            // e_ij = (Ra, ta) * inv(Tij): R = Ra*TR^T, t = ta - R*Tt
            {
                float* pv = sP + (2 * e) * 12;
#pragma unroll
                for (int r = 0; r < 3; r++) {
                    float re[3];
#pragma unroll
                    for (int c = 0; c < 3; c++)
                        re[c] = Ra[r * 3 + 0] * TRm[c * 3 + 0]
                              + Ra[r * 3 + 1] * TRm[c * 3 + 1]
                              + Ra[r * 3 + 2] * TRm[c * 3 + 2];
                    float te = ta[r] - (re[0] * Tt[0] + re[1] * Tt[1] + re[2] * Tt[2]);
                    pv[4 * r + 0] = re[0]; pv[4 * r + 1] = re[1];
                    pv[4 * r + 2] = re[2]; pv[4 * r + 3] = te;
                }
            }
            // e_ji: Rb = Ra^T, tb = ti - Rb*tj; R = Rb*TR, t = Rb*Tt + tb
            {
                float* pv = sP + (2 * e + 1) * 12;
#pragma unroll
                for (int r = 0; r < 3; r++) {
                    float bv0 = Ra[0 * 3 + r], bv1 = Ra[1 * 3 + r], bv2 = Ra[2 * 3 + r];
                    float tb = ti[r] - (bv0 * tj[0] + bv1 * tj[1] + bv2 * tj[2]);
                    float re[3];
#pragma unroll
                    for (int c = 0; c < 3; c++)
                        re[c] = bv0 * TRm[0 * 3 + c] + bv1 * TRm[1 * 3 + c] + bv2 * TRm[2 * 3 + c];
                    float te = bv0 * Tt[0] + bv1 * Tt[1] + bv2 * Tt[2] + tb;
                    pv[4 * r + 0] = re[0]; pv[4 * r + 1] = re[1];
                    pv[4 * r + 2] = re[2]; pv[4 * r + 3] = te;
                }
            }
        }
        __syncthreads();

        // -------- phase 3: H1 (layer 1 + relu), warp = edge-group -----------
#pragma unroll
        for (int m = 0; m < 4; m++) {
            const int e = warp + 20 * m;
            const int gi = sTgt[2 * e + 1], gj = sTgt[2 * e];
            const ulonglong2 Ai = ((const ulonglong2*)(g_AB + (size_t)gi * 256))[lane];
            const ulonglong2 Bj = ((const ulonglong2*)(g_AB + (size_t)gj * 256 + 128))[lane];
            const ulonglong2 Aj = ((const ulonglong2*)(g_AB + (size_t)gj * 256))[lane];
            const ulonglong2 Bi = ((const ulonglong2*)(g_AB + (size_t)gi * 256 + 128))[lane];

            ull et0 = 0ull, et1 = 0ull;
            const float* efr = sEF + e * 32;
#pragma unroll 8
            for (int k = 0; k < 32; k++) {
                ulonglong2 w = *(const ulonglong2*)(sW1e + k * 128 + 4 * lane);
                ull e2; PACK2(e2, efr[k]);
                FMA2(et0, e2, w.x); FMA2(et1, e2, w.y);
            }
            ull q0 = 0ull, q1 = 0ull, p0 = 0ull, p1 = 0ull;
            const float* pr = sP + (2 * e) * 12;
#pragma unroll
            for (int k = 0; k < 12; k++) {
                ulonglong2 w = *(const ulonglong2*)(sW1p + k * 128 + 4 * lane);
                ull a2; PACK2(a2, pr[k]);
                ull c2; PACK2(c2, pr[12 + k]);
                FMA2(q0, a2, w.x); FMA2(q1, a2, w.y);
                FMA2(p0, c2, w.x); FMA2(p1, c2, w.y);
            }
            ull s0, s1, t0, t1;
            ADD2(s0, Ai.x, Bj.x); ADD2(s0, s0, et0); ADD2(s0, s0, q0); ADD2(s0, s0, b1p.x);
            ADD2(s1, Ai.y, Bj.y); ADD2(s1, s1, et1); ADD2(s1, s1, q1); ADD2(s1, s1, b1p.y);
            ADD2(t0, Aj.x, Bi.x); ADD2(t0, t0, et0); ADD2(t0, t0, p0); ADD2(t0, t0, b1p.x);
            ADD2(t1, Aj.y, Bi.y); ADD2(t1, t1, et1); ADD2(t1, t1, p1); ADD2(t1, t1, b1p.y);
            float4 hij, hji;
            UNPK2(hij.x, hij.y, s0); UNPK2(hij.z, hij.w, s1);
            UNPK2(hji.x, hji.y, t0); UNPK2(hji.z, hji.w, t1);
            ((float4*)(sH1 + (size_t)(2 * e) * 132))[lane]     = relu4(hij);
            ((float4*)(sH1 + (size_t)(2 * e + 1) * 132))[lane] = relu4(hji);
        }
        __syncthreads();

        // -------- phase 4: layer 2 GEMM (160 rows x 128 x 128) + scatter ----
        const float* hb = sH1 + (size_t)(8 * warp) * 132;
        ull acc[8][2];
#pragma unroll
        for (int r = 0; r < 8; r++) { acc[r][0] = b2p.x; acc[r][1] = b2p.y; }
#pragma unroll 2
        for (int k = 0; k < 128; k += 4) {
            ulonglong2 w0 = *(const ulonglong2*)(sW2 + (k + 0) * 128 + 4 * lane);
            ulonglong2 w1 = *(const ulonglong2*)(sW2 + (k + 1) * 128 + 4 * lane);
            ulonglong2 w2 = *(const ulonglong2*)(sW2 + (k + 2) * 128 + 4 * lane);
            ulonglong2 w3 = *(const ulonglong2*)(sW2 + (k + 3) * 128 + 4 * lane);
#pragma unroll
            for (int r = 0; r < 8; r++) {
                float4 h4 = *(const float4*)(hb + r * 132 + k);  // broadcast
                ull h0; PACK2(h0, h4.x);
                FMA2(acc[r][0], h0, w0.x); FMA2(acc[r][1], h0, w0.y);
                ull h1; PACK2(h1, h4.y);
                FMA2(acc[r][0], h1, w1.x); FMA2(acc[r][1], h1, w1.y);
                ull h2; PACK2(h2, h4.z);
                FMA2(acc[r][0], h2, w2.x); FMA2(acc[r][1], h2, w2.y);
                ull h3; PACK2(h3, h4.w);
                FMA2(acc[r][0], h3, w3.x); FMA2(acc[r][1], h3, w3.y);
            }
        }
#pragma unroll
        for (int r = 0; r < 8; r++) {
            const int row = 8 * warp + r;
            const int tgt = sTgt[row];
            float4 o;
            UNPK2(o.x, o.y, acc[r][0]); UNPK2(o.z, o.w, acc[r][1]);
            red_add_v4(g_accum + (size_t)tgt * 128 + 4 * lane, relu4(o));
            if (lane == 0) atomicAdd(&g_cnt[tgt], 1.0f);
        }
    }
}

// ---------------------------------------------------------------------------
// Kernel 3: node MLP (224->128->70) + SE3 epilogue + output assembly
// block = 256 threads, tile = 32 nodes, W3/W4 in smem (proven R6 config)
// ---------------------------------------------------------------------------
#define NO_W3  0       // 224*128 = 28672
#define NO_W4  28672   // 128*96  = 12288 (cols padded 70->96 with zeros)
#define NO_B3  40960   // 128
#define NO_B4  41088   // 96 (padded)
#define NO_U   41184   // 16*32 = 512
#define NO_G   41696   // 32*228 = 7296
#define NO_H3  48992   // 32*132 = 4224
#define NO_OUT 53216   // 32*72  = 2304
#define NODE_SMEM ((53216 + 2304) * 4)   // 222,080 B

__global__ void __launch_bounds__(256, 1)
k_node(const float* __restrict__ xfeat, const float* __restrict__ T_R,
       const float* __restrict__ T_t, const float* __restrict__ u,
       const int* __restrict__ batch,
       const float* __restrict__ W3, const float* __restrict__ b3,
       const float* __restrict__ W4, const float* __restrict__ b4,
       float* __restrict__ out) {
    extern __shared__ float sm[];
    float* sW3 = sm + NO_W3;
    float* sW4 = sm + NO_W4;
    float* sb3 = sm + NO_B3;
    float* sb4 = sm + NO_B4;
    float* sU  = sm + NO_U;
    float* sG  = sm + NO_G;    // stride 228
    float* sH3 = sm + NO_H3;   // stride 132
    float* sO  = sm + NO_OUT;  // stride 72

    const int tid = threadIdx.x;
    for (int idx = tid; idx < 28672 / 4; idx += 256)
        ((float4*)sW3)[idx] = ((const float4*)W3)[idx];
    for (int idx = tid; idx < 128 * 96; idx += 256) {
        int k = idx / 96, c = idx % 96;
        sW4[idx] = (c < 70) ? W4[k * 70 + c] : 0.f;
    }
    if (tid < 128) sb3[tid] = b3[tid];
    if (tid < 96)  sb4[tid] = (tid < 70) ? b4[tid] : 0.f;
    for (int idx = tid; idx < 512; idx += 256) sU[idx] = u[idx];
    __syncthreads();

    const int warp = tid >> 5, lane = tid & 31;
    const ulonglong2 b3p = *(const ulonglong2*)(sb3 + 4 * lane);

    for (int tile = blockIdx.x; tile < NN / 32; tile += gridDim.x) {
        const int nb = tile * 32;
        __syncthreads();

        // build G = [aggr(128) | xfeat(64) | u[batch](32)]
        for (int idx = tid; idx < 1024; idx += 256) {
            int n = idx >> 5, c4 = idx & 31;
            int gn = nb + n;
            float4 s = ((const float4*)(g_accum + (size_t)gn * 128))[c4];
            float inv = 1.f / fmaxf(g_cnt[gn], 1.f);
            s.x *= inv; s.y *= inv; s.z *= inv; s.w *= inv;
            ((float4*)(sG + n * 228))[c4] = s;
        }
        for (int idx = tid; idx < 512; idx += 256) {
            int n = idx >> 4, c4 = idx & 15;
            ((float4*)(sG + n * 228 + 128))[c4] =
                ((const float4*)(xfeat + (size_t)(nb + n) * 64))[c4];
        }
        {
            int n = tid >> 3, c4 = tid & 7;
            int bn = batch[nb + n];
            ((float4*)(sG + n * 228 + 192))[c4] = ((const float4*)(sU + bn * 32))[c4];
        }
        __syncthreads();

        // GEMM1: H3 = relu(G @ W3 + b3), rows 4w..4w+3, cols 4*lane (packed)
        {
            ull acc[4][2];
#pragma unroll
            for (int r = 0; r < 4; r++) { acc[r][0] = b3p.x; acc[r][1] = b3p.y; }
#pragma unroll 4
            for (int k = 0; k < 224; k++) {
                ulonglong2 w = *(const ulonglong2*)(sW3 + k * 128 + 4 * lane);
#pragma unroll
                for (int r = 0; r < 4; r++) {
                    ull g2; PACK2(g2, sG[(4 * warp + r) * 228 + k]);
                    FMA2(acc[r][0], g2, w.x); FMA2(acc[r][1], g2, w.y);
                }
            }
#pragma unroll
            for (int r = 0; r < 4; r++) {
                float4 o;
                UNPK2(o.x, o.y, acc[r][0]); UNPK2(o.z, o.w, acc[r][1]);
                ((float4*)(sH3 + (4 * warp + r) * 132))[lane] = relu4(o);
            }
        }
        __syncthreads();

        // GEMM2: OUT = H3 @ W4 + b4 (70 cols, padded to 96)
        {
            float a0[4], a1[4], a2[4];
            float b40 = sb4[lane], b41 = sb4[32 + lane], b42 = sb4[64 + lane];
#pragma unroll
            for (int r = 0; r < 4; r++) { a0[r] = b40; a1[r] = b41; a2[r] = b42; }
#pragma unroll 4
            for (int k = 0; k < 128; k++) {
                const float* wr = sW4 + k * 96;
                float w0 = wr[lane], w1 = wr[32 + lane], w2 = wr[64 + lane];
#pragma unroll
                for (int r = 0; r < 4; r++) {
                    float h = sH3[(4 * warp + r) * 132 + k];
                    a0[r] = fmaf(h, w0, a0[r]);
                    a1[r] = fmaf(h, w1, a1[r]);
                    a2[r] = fmaf(h, w2, a2[r]);
                }
            }
#pragma unroll
            for (int r = 0; r < 4; r++) {
                float* orow = sO + (4 * warp + r) * 72;
                orow[lane] = a0[r];
                orow[32 + lane] = a1[r];
                if (lane < 6) orow[64 + lane] = a2[r];
            }
        }
        __syncthreads();

        // epilogue: xfeat_out = xfeat + xupd
        for (int idx = tid; idx < 2048; idx += 256) {
            int n = idx >> 6, c = idx & 63;
            int gn = nb + n;
            out[(size_t)gn * 77 + c] = xfeat[(size_t)gn * 64 + c] + sO[n * 72 + c];
        }
        // SE3 exp + compose, one thread per node
        if (tid < 32) {
            const int n = tid, gn = nb + n;
            const float* orow = sO + n * 72;
            float rho0 = orow[64], rho1 = orow[65], rho2 = orow[66];
            float p0 = orow[67], p1 = orow[68], p2 = orow[69];
            float th0 = sqrtf(p0 * p0 + p1 * p1 + p2 * p2);
            float s = PI_F * tanhf(th0 / PI_F) / (th0 + 1e-8f);
            p0 *= s; p1 *= s; p2 *= s;
            float th2 = p0 * p0 + p1 * p1 + p2 * p2;
            float th = sqrtf(th2 + 1e-12f);
            float a, b, c;
            if (th < 1e-4f) {
                a = 1.f - th2 / 6.f;
                b = 0.5f - th2 / 24.f;
                c = 1.f / 6.f - th2 / 120.f;
            } else {
                float sth = sinf(th), cth = cosf(th);
                a = sth / th;
                b = (1.f - cth) / th2;
                c = (th - sth) / (th2 * th);
            }
            float R[9], V[9];
            R[0] = 1.f + b * (p0 * p0 - th2); R[1] = -a * p2 + b * p0 * p1; R[2] =  a * p1 + b * p0 * p2;
            R[3] =  a * p2 + b * p1 * p0;    R[4] = 1.f + b * (p1 * p1 - th2); R[5] = -a * p0 + b * p1 * p2;
            R[6] = -a * p1 + b * p2 * p0;    R[7] =  a * p0 + b * p2 * p1; R[8] = 1.f + b * (p2 * p2 - th2);
            V[0] = 1.f + c * (p0 * p0 - th2); V[1] = -b * p2 + c * p0 * p1; V[2] =  b * p1 + c * p0 * p2;
            V[3] =  b * p2 + c * p1 * p0;    V[4] = 1.f + c * (p1 * p1 - th2); V[5] = -b * p0 + c * p1 * p2;
            V[6] = -b * p1 + c * p2 * p0;    V[7] =  b * p0 + c * p2 * p1; V[8] = 1.f + c * (p2 * p2 - th2);
            float td0 = V[0] * rho0 + V[1] * rho1 + V[2] * rho2;
            float td1 = V[3] * rho0 + V[4] * rho1 + V[5] * rho2;
            float td2 = V[6] * rho0 + V[7] * rho1 + V[8] * rho2;

            float TRn[9], Ttn[3];
#pragma unroll
            for (int k = 0; k < 9; k++) TRn[k] = T_R[(size_t)gn * 9 + k];
#pragma unroll
            for (int k = 0; k < 3; k++) Ttn[k] = T_t[(size_t)gn * 3 + k];

            float* op = out + (size_t)gn * 77 + 64;
#pragma unroll
            for (int r = 0; r < 3; r++) {
#pragma unroll
                for (int cc = 0; cc < 3; cc++)
                    op[3 * r + cc] = R[r * 3 + 0] * TRn[0 * 3 + cc]
                                   + R[r * 3 + 1] * TRn[1 * 3 + cc]
                                   + R[r * 3 + 2] * TRn[2 * 3 + cc];
            }
            float tdv[3] = {td0, td1, td2};
#pragma unroll
            for (int r = 0; r < 3; r++)
                op[9 + r] = R[r * 3 + 0] * Ttn[0] + R[r * 3 + 1] * Ttn[1]
                          + R[r * 3 + 2] * Ttn[2] + tdv[r];
            op[12] = sqrtf(th2);
        }
    }
}

// ---------------------------------------------------------------------------
// Host launcher
// ---------------------------------------------------------------------------
extern "C" void kernel_launch(void* const* d_in, const int* in_sizes, int n_in,
                              void* d_out, int out_size) {
    (void)in_sizes; (void)n_in; (void)out_size;
    const float* xfeat     = (const float*)d_in[0];
    const float* T_R       = (const float*)d_in[1];
    const float* T_t       = (const float*)d_in[2];
    const float* edge_feat = (const float*)d_in[3];
    const float* Tij_R     = (const float*)d_in[4];
    const float* Tij_t     = (const float*)d_in[5];
    const float* u         = (const float*)d_in[6];
    const int*   edge_idx  = (const int*)d_in[7];
    const int*   batch     = (const int*)d_in[8];
    const float* W1 = (const float*)d_in[9];
    const float* b1 = (const float*)d_in[10];
    const float* W2 = (const float*)d_in[11];
    const float* b2 = (const float*)d_in[12];
    const float* W3 = (const float*)d_in[13];
    const float* b3 = (const float*)d_in[14];
    const float* W4 = (const float*)d_in[15];
    const float* b4 = (const float*)d_in[16];
    float* out = (float*)d_out;

    cudaFuncSetAttribute(k_pre,  cudaFuncAttributeMaxDynamicSharedMemorySize, PRE_SMEM);
    cudaFuncSetAttribute(k_edge, cudaFuncAttributeMaxDynamicSharedMemorySize, EDGE_SMEM);
    cudaFuncSetAttribute(k_node, cudaFuncAttributeMaxDynamicSharedMemorySize, NODE_SMEM);

    k_pre<<<296, 256, PRE_SMEM>>>(xfeat, W1);
    k_edge<<<148, 640, EDGE_SMEM>>>(T_R, T_t, edge_feat, Tij_R, Tij_t,
                                    edge_idx, W1, b1, W2, b2);
    k_node<<<148, 256, NODE_SMEM>>>(xfeat, T_R, T_t, u, batch,
                                    W3, b3, W4, b4, out);
}

// round 17
// speedup vs baseline: 1.4658x; 1.1464x over previous
#include <cuda_runtime.h>
#include <math.h>

// Problem constants
#define NN 20000
#define EE 200000
#define BBATCH 16
#define ND 64
#define ED 32
#define GD 32
#define HD 128
#define DOF 6
#define PI_F 3.14159265358979f

typedef unsigned long long ull;

// ---------------------------------------------------------------------------
// Scratch (static __device__ arrays; no allocation allowed)
// ---------------------------------------------------------------------------
__device__ float g_AB[(size_t)NN * 256];     // per-node A (x@W1a) [0:128], B (x@W1b) [128:256]
__device__ float g_accum[(size_t)NN * HD];   // segment sums
__device__ float g_cnt[NN];                  // segment counts

// ---- packed f32x2 helpers ----
#define PACK2(d, s)      asm("mov.b64 %0, {%1, %1};" : "=l"(d) : "f"(s))
#define UNPK2(lo, hi, v) asm("mov.b64 {%0, %1}, %2;" : "=f"(lo), "=f"(hi) : "l"(v))
#define FMA2(acc, a, b)  asm("fma.rn.f32x2 %0, %1, %2, %0;" : "+l"(acc) : "l"(a), "l"(b))
#define ADD2(d, a, b)    asm("add.rn.f32x2 %0, %1, %2;" : "=l"(d) : "l"(a), "l"(b))

__device__ __forceinline__ float4 relu4(float4 v) {
    v.x = fmaxf(v.x, 0.f); v.y = fmaxf(v.y, 0.f);
    v.z = fmaxf(v.z, 0.f); v.w = fmaxf(v.w, 0.f);
    return v;
}

__device__ __forceinline__ void red_add_v4(float* p, float4 v) {
    asm volatile("red.global.add.v4.f32 [%0], {%1,%2,%3,%4};"
                 :: "l"(p), "f"(v.x), "f"(v.y), "f"(v.z), "f"(v.w) : "memory");
}

// ---------------------------------------------------------------------------
// Kernel 1: per-node A = x@W1[0:64], B = x@W1[64:128]; zero accum/cnt
// block = 256 threads, tile = 32 nodes, grid = 296 (2 blocks/SM, W1 in smem)
// — measured-best k_pre configuration (~30us).
// ---------------------------------------------------------------------------
#define PRE_SMEM ((128 * 128 + 32 * 68) * 4)

__global__ void __launch_bounds__(256, 2)
k_pre(const float* __restrict__ xfeat, const float* __restrict__ W1) {
    extern __shared__ float sm[];
    float* sW = sm;              // 128*128
    float* sX = sm + 128 * 128;  // 32*68 (padded)

    for (int idx = threadIdx.x; idx < (128 * 128) / 4; idx += 256)
        ((float4*)sW)[idx] = ((const float4*)W1)[idx];

    const int warp = threadIdx.x >> 5, lane = threadIdx.x & 31;
    const int NT = NN / 32;   // 625

    for (int tile = blockIdx.x; tile < NT; tile += gridDim.x) {
        const int nb = tile * 32;
        __syncthreads();
        for (int idx = threadIdx.x; idx < 32 * 16; idx += 256) {
            int n = idx >> 4, k4 = idx & 15;
            ((float4*)(sX + n * 68))[k4] =
                ((const float4*)(xfeat + (size_t)(nb + n) * 64))[k4];
        }
        __syncthreads();

        ull accA[4][2], accB[4][2];
#pragma unroll
        for (int r = 0; r < 4; r++) {
            accA[r][0] = 0ull; accA[r][1] = 0ull;
            accB[r][0] = 0ull; accB[r][1] = 0ull;
        }
#pragma unroll 4
        for (int k = 0; k < 64; k++) {
            ulonglong2 wa = *(const ulonglong2*)(sW + k * 128 + 4 * lane);
            ulonglong2 wb = *(const ulonglong2*)(sW + (64 + k) * 128 + 4 * lane);
#pragma unroll
            for (int r = 0; r < 4; r++) {
                float x = sX[(4 * warp + r) * 68 + k];
                ull xx; PACK2(xx, x);
                FMA2(accA[r][0], xx, wa.x); FMA2(accA[r][1], xx, wa.y);
                FMA2(accB[r][0], xx, wb.x); FMA2(accB[r][1], xx, wb.y);
            }
        }
#pragma unroll
        for (int r = 0; r < 4; r++) {
            int gn = nb + 4 * warp + r;
            float4 oa, ob;
            UNPK2(oa.x, oa.y, accA[r][0]); UNPK2(oa.z, oa.w, accA[r][1]);
            UNPK2(ob.x, ob.y, accB[r][0]); UNPK2(ob.z, ob.w, accB[r][1]);
            ((float4*)(g_AB + (size_t)gn * 256))[lane] = oa;
            ((float4*)(g_AB + (size_t)gn * 256 + 128))[lane] = ob;
            ((float4*)(g_accum + (size_t)gn * 128))[lane] = make_float4(0.f, 0.f, 0.f, 0.f);
            if (lane == 0) g_cnt[gn] = 0.f;
        }
    }
}

// ---------------------------------------------------------------------------
// Kernel 2: fused edge MLP — WARP-AUTONOMOUS version.
// block = 640 threads (20 warps), 1 block/SM. Each warp owns 4 consecutive
// edges (8 rows) end-to-end; all cross-lane data flows through warp-private
// smem with __syncwarp only. NO __syncthreads in the main loop -> warps
// free-run and hide each other's pose/gather latency.
// ---------------------------------------------------------------------------
// smem float offsets
#define EO_W2   0       // 128*128 = 16384
#define EO_W1E  16384   // 32*128  = 4096
#define EO_W1P  20480   // 12*128  = 1536
#define EO_B1   22016   // 128
#define EO_B2   22144   // 128
#define EO_EF   22272   // 20 warps * 128 = 2560
#define EO_P    24832   // 20 warps * 96  = 1920
#define EO_TGT  26752   // 20 warps * 8 ints = 160
#define EO_H1   26912   // 20 warps * 8*132 = 21120
#define EDGE_SMEM ((26912 + 21120) * 4)   // 192,128 B

#define NWARPS 20

__global__ void __launch_bounds__(640, 1)
k_edge(const float* __restrict__ T_R, const float* __restrict__ T_t,
       const float* __restrict__ edge_feat,
       const float* __restrict__ Tij_R, const float* __restrict__ Tij_t,
       const int* __restrict__ edge_index,
       const float* __restrict__ W1, const float* __restrict__ b1,
       const float* __restrict__ W2, const float* __restrict__ b2) {
    extern __shared__ float sm[];
    float* sW2  = sm + EO_W2;
    float* sW1e = sm + EO_W1E;
    float* sW1p = sm + EO_W1P;
    float* sb1  = sm + EO_B1;
    float* sb2  = sm + EO_B2;

    const int tid = threadIdx.x;
    for (int idx = tid; idx < 16384 / 4; idx += 640)
        ((float4*)sW2)[idx] = ((const float4*)W2)[idx];
    for (int idx = tid; idx < 4096 / 4; idx += 640)
        ((float4*)sW1e)[idx] = ((const float4*)(W1 + 128 * 128))[idx];
    for (int idx = tid; idx < 1536 / 4; idx += 640)
        ((float4*)sW1p)[idx] = ((const float4*)(W1 + 160 * 128))[idx];
    if (tid < 128) { sb1[tid] = b1[tid]; sb2[tid] = b2[tid]; }
    __syncthreads();   // the ONLY block barrier

    const int warp = tid >> 5, lane = tid & 31;
    const ulonglong2 b1p = *(const ulonglong2*)(sb1 + 4 * lane);
    const ulonglong2 b2p = *(const ulonglong2*)(sb2 + 4 * lane);

    // warp-private scratch
    float* EFw = sm + EO_EF + warp * 128;   // 4 edges * 32 floats
    float* Pw  = sm + EO_P  + warp * 96;    // 4 edges * 24 floats (ij|ji)
    int*   Tw  = (int*)(sm + EO_TGT) + warp * 8;
    float* Hw  = sm + EO_H1 + warp * 1056;  // 8 rows * 132

    const int NG = EE / 4;                   // 50000 4-edge groups
    const int gw0 = blockIdx.x * NWARPS + warp;
    const int gstride = gridDim.x * NWARPS;

    for (int grp = gw0; grp < NG; grp += gstride) {
        const int e0 = grp * 4;

        // ---- stage 1: edge_feat (coalesced: 4 consecutive edges = 128 floats)
        ((float4*)EFw)[lane] = ((const float4*)(edge_feat + (size_t)e0 * 32))[lane];

        // ---- stage 2: pose, lanes 0-3 (one edge each) ----------------------
        if (lane < 4) {
            const int e = lane, ge = e0 + e;
            const int gi = edge_index[ge];
            const int gj = edge_index[EE + ge];
            Tw[2 * e]     = gj;   // f_ij aggregates into j
            Tw[2 * e + 1] = gi;   // f_ji aggregates into i

            float Ri[9], Rj[9], TRm[9], ti[3], tj[3], Tt[3];
#pragma unroll
            for (int k = 0; k < 9; k++) {
                Ri[k]  = T_R[(size_t)gi * 9 + k];
                Rj[k]  = T_R[(size_t)gj * 9 + k];
                TRm[k] = Tij_R[(size_t)ge * 9 + k];
            }
#pragma unroll
            for (int k = 0; k < 3; k++) {
                ti[k] = T_t[(size_t)gi * 3 + k];
                tj[k] = T_t[(size_t)gj * 3 + k];
                Tt[k] = Tij_t[(size_t)ge * 3 + k];
            }
            // Ra = Rj * Ri^T ; ta = tj - Ra*ti
            float Ra[9], ta[3];
#pragma unroll
            for (int r = 0; r < 3; r++) {
#pragma unroll
                for (int c = 0; c < 3; c++)
                    Ra[r * 3 + c] = Rj[r * 3 + 0] * Ri[c * 3 + 0]
                                  + Rj[r * 3 + 1] * Ri[c * 3 + 1]
                                  + Rj[r * 3 + 2] * Ri[c * 3 + 2];
                ta[r] = tj[r] - (Ra[r * 3 + 0] * ti[0] + Ra[r * 3 + 1] * ti[1]
                               + Ra[r * 3 + 2] * ti[2]);
            }
            // e_ij = (Ra, ta) * inv(Tij): R = Ra*TR^T, t = ta - R*Tt
            {
                float* pv = Pw + e * 24;
#pragma unroll
                for (int r = 0; r < 3; r++) {
                    float re[3];
#pragma unroll
                    for (int c = 0; c < 3; c++)
                        re[c] = Ra[r * 3 + 0] * TRm[c * 3 + 0]
                              + Ra[r * 3 + 1] * TRm[c * 3 + 1]
                              + Ra[r * 3 + 2] * TRm[c * 3 + 2];
                    float te = ta[r] - (re[0] * Tt[0] + re[1] * Tt[1] + re[2] * Tt[2]);
                    pv[4 * r + 0] = re[0]; pv[4 * r + 1] = re[1];
                    pv[4 * r + 2] = re[2]; pv[4 * r + 3] = te;
                }
            }
            // e_ji: Rb = Ra^T, tb = ti - Rb*tj; R = Rb*TR, t = Rb*Tt + tb
            {
                float* pv = Pw + e * 24 + 12;
#pragma unroll
                for (int r = 0; r < 3; r++) {
                    float bv0 = Ra[0 * 3 + r], bv1 = Ra[1 * 3 + r], bv2 = Ra[2 * 3 + r];
                    float tb = ti[r] - (bv0 * tj[0] + bv1 * tj[1] + bv2 * tj[2]);
                    float re[3];
#pragma unroll
                    for (int c = 0; c < 3; c++)
                        re[c] = bv0 * TRm[0 * 3 + c] + bv1 * TRm[1 * 3 + c] + bv2 * TRm[2 * 3 + c];
                    float te = bv0 * Tt[0] + bv1 * Tt[1] + bv2 * Tt[2] + tb;
                    pv[4 * r + 0] = re[0]; pv[4 * r + 1] = re[1];
                    pv[4 * r + 2] = re[2]; pv[4 * r + 3] = te;
                }
            }
        }
        __syncwarp();

        // ---- stage 3: H1 (layer 1 + relu), 4 edges -> rows 0..7 of Hw ------
#pragma unroll
        for (int m = 0; m < 4; m++) {
            const int gi = Tw[2 * m + 1], gj = Tw[2 * m];
            const ulonglong2 Ai = ((const ulonglong2*)(g_AB + (size_t)gi * 256))[lane];
            const ulonglong2 Bj = ((const ulonglong2*)(g_AB + (size_t)gj * 256 + 128))[lane];
            const ulonglong2 Aj = ((const ulonglong2*)(g_AB + (size_t)gj * 256))[lane];
            const ulonglong2 Bi = ((const ulonglong2*)(g_AB + (size_t)gi * 256 + 128))[lane];

            ull et0 = 0ull, et1 = 0ull;
            const float* efr = EFw + m * 32;
#pragma unroll 8
            for (int k = 0; k < 32; k++) {
                ulonglong2 w = *(const ulonglong2*)(sW1e + k * 128 + 4 * lane);
                ull e2; PACK2(e2, efr[k]);
                FMA2(et0, e2, w.x); FMA2(et1, e2, w.y);
            }
            ull q0 = 0ull, q1 = 0ull, p0 = 0ull, p1 = 0ull;
            const float* pr = Pw + m * 24;
#pragma unroll
            for (int k = 0; k < 12; k++) {
                ulonglong2 w = *(const ulonglong2*)(sW1p + k * 128 + 4 * lane);
                ull a2; PACK2(a2, pr[k]);
                ull c2; PACK2(c2, pr[12 + k]);
                FMA2(q0, a2, w.x); FMA2(q1, a2, w.y);
                FMA2(p0, c2, w.x); FMA2(p1, c2, w.y);
            }
            ull s0, s1, t0, t1;
            ADD2(s0, Ai.x, Bj.x); ADD2(s0, s0, et0); ADD2(s0, s0, q0); ADD2(s0, s0, b1p.x);
            ADD2(s1, Ai.y, Bj.y); ADD2(s1, s1, et1); ADD2(s1, s1, q1); ADD2(s1, s1, b1p.y);
            ADD2(t0, Aj.x, Bi.x); ADD2(t0, t0, et0); ADD2(t0, t0, p0); ADD2(t0, t0, b1p.x);
            ADD2(t1, Aj.y, Bi.y); ADD2(t1, t1, et1); ADD2(t1, t1, p1); ADD2(t1, t1, b1p.y);
            float4 hij, hji;
            UNPK2(hij.x, hij.y, s0); UNPK2(hij.z, hij.w, s1);
            UNPK2(hji.x, hji.y, t0); UNPK2(hji.z, hji.w, t1);
            ((float4*)(Hw + (size_t)(2 * m) * 132))[lane]     = relu4(hij);
            ((float4*)(Hw + (size_t)(2 * m + 1) * 132))[lane] = relu4(hji);
        }
        __syncwarp();

        // ---- stage 4: layer 2 GEMM (8 rows x 128 x 128) + scatter ----------
        ull acc[8][2];
#pragma unroll
        for (int r = 0; r < 8; r++) { acc[r][0] = b2p.x; acc[r][1] = b2p.y; }
#pragma unroll 2
        for (int k = 0; k < 128; k += 4) {
            ulonglong2 w0 = *(const ulonglong2*)(sW2 + (k + 0) * 128 + 4 * lane);
            ulonglong2 w1 = *(const ulonglong2*)(sW2 + (k + 1) * 128 + 4 * lane);
            ulonglong2 w2 = *(const ulonglong2*)(sW2 + (k + 2) * 128 + 4 * lane);
            ulonglong2 w3 = *(const ulonglong2*)(sW2 + (k + 3) * 128 + 4 * lane);
#pragma unroll
            for (int r = 0; r < 8; r++) {
                float4 h4 = *(const float4*)(Hw + r * 132 + k);  // broadcast
                ull h0; PACK2(h0, h4.x);
                FMA2(acc[r][0], h0, w0.x); FMA2(acc[r][1], h0, w0.y);
                ull h1; PACK2(h1, h4.y);
                FMA2(acc[r][0], h1, w1.x); FMA2(acc[r][1], h1, w1.y);
                ull h2; PACK2(h2, h4.z);
                FMA2(acc[r][0], h2, w2.x); FMA2(acc[r][1], h2, w2.y);
                ull h3; PACK2(h3, h4.w);
                FMA2(acc[r][0], h3, w3.x); FMA2(acc[r][1], h3, w3.y);
            }
        }
#pragma unroll
        for (int r = 0; r < 8; r++) {
            const int tgt = Tw[r];
            float4 o;
            UNPK2(o.x, o.y, acc[r][0]); UNPK2(o.z, o.w, acc[r][1]);
            red_add_v4(g_accum + (size_t)tgt * 128 + 4 * lane, relu4(o));
            if (lane == 0) atomicAdd(&g_cnt[tgt], 1.0f);
        }
        __syncwarp();   // protect EFw/Pw/Hw reuse next iteration
    }
}

// ---------------------------------------------------------------------------
// Kernel 3: node MLP (224->128->70) + SE3 epilogue + output assembly
// block = 256 threads, tile = 32 nodes, W3/W4 in smem (proven R6 config)
// ---------------------------------------------------------------------------
#define NO_W3  0       // 224*128 = 28672
#define NO_W4  28672   // 128*96  = 12288 (cols padded 70->96 with zeros)
#define NO_B3  40960   // 128
#define NO_B4  41088   // 96 (padded)
#define NO_U   41184   // 16*32 = 512
#define NO_G   41696   // 32*228 = 7296
#define NO_H3  48992   // 32*132 = 4224
#define NO_OUT 53216   // 32*72  = 2304
#define NODE_SMEM ((53216 + 2304) * 4)   // 222,080 B

__global__ void __launch_bounds__(256, 1)
k_node(const float* __restrict__ xfeat, const float* __restrict__ T_R,
       const float* __restrict__ T_t, const float* __restrict__ u,
       const int* __restrict__ batch,
       const float* __restrict__ W3, const float* __restrict__ b3,
       const float* __restrict__ W4, const float* __restrict__ b4,
       float* __restrict__ out) {
    extern __shared__ float sm[];
    float* sW3 = sm + NO_W3;
    float* sW4 = sm + NO_W4;
    float* sb3 = sm + NO_B3;
    float* sb4 = sm + NO_B4;
    float* sU  = sm + NO_U;
    float* sG  = sm + NO_G;    // stride 228
    float* sH3 = sm + NO_H3;   // stride 132
    float* sO  = sm + NO_OUT;  // stride 72

    const int tid = threadIdx.x;
    for (int idx = tid; idx < 28672 / 4; idx += 256)
        ((float4*)sW3)[idx] = ((const float4*)W3)[idx];
    for (int idx = tid; idx < 128 * 96; idx += 256) {
        int k = idx / 96, c = idx % 96;
        sW4[idx] = (c < 70) ? W4[k * 70 + c] : 0.f;
    }
    if (tid < 128) sb3[tid] = b3[tid];
    if (tid < 96)  sb4[tid] = (tid < 70) ? b4[tid] : 0.f;
    for (int idx = tid; idx < 512; idx += 256) sU[idx] = u[idx];
    __syncthreads();

    const int warp = tid >> 5, lane = tid & 31;
    const ulonglong2 b3p = *(const ulonglong2*)(sb3 + 4 * lane);

    for (int tile = blockIdx.x; tile < NN / 32; tile += gridDim.x) {
        const int nb = tile * 32;
        __syncthreads();

        // build G = [aggr(128) | xfeat(64) | u[batch](32)]
        for (int idx = tid; idx < 1024; idx += 256) {
            int n = idx >> 5, c4 = idx & 31;
            int gn = nb + n;
            float4 s = ((const float4*)(g_accum + (size_t)gn * 128))[c4];
            float inv = 1.f / fmaxf(g_cnt[gn], 1.f);
            s.x *= inv; s.y *= inv; s.z *= inv; s.w *= inv;
            ((float4*)(sG + n * 228))[c4] = s;
        }
        for (int idx = tid; idx < 512; idx += 256) {
            int n = idx >> 4, c4 = idx & 15;
            ((float4*)(sG + n * 228 + 128))[c4] =
                ((const float4*)(xfeat + (size_t)(nb + n) * 64))[c4];
        }
        {
            int n = tid >> 3, c4 = tid & 7;
            int bn = batch[nb + n];
            ((float4*)(sG + n * 228 + 192))[c4] = ((const float4*)(sU + bn * 32))[c4];
        }
        __syncthreads();

        // GEMM1: H3 = relu(G @ W3 + b3), rows 4w..4w+3, cols 4*lane (packed)
        {
            ull acc[4][2];
#pragma unroll
            for (int r = 0; r < 4; r++) { acc[r][0] = b3p.x; acc[r][1] = b3p.y; }
#pragma unroll 4
            for (int k = 0; k < 224; k++) {
                ulonglong2 w = *(const ulonglong2*)(sW3 + k * 128 + 4 * lane);
#pragma unroll
                for (int r = 0; r < 4; r++) {
                    ull g2; PACK2(g2, sG[(4 * warp + r) * 228 + k]);
                    FMA2(acc[r][0], g2, w.x); FMA2(acc[r][1], g2, w.y);
                }
            }
#pragma unroll
            for (int r = 0; r < 4; r++) {
                float4 o;
                UNPK2(o.x, o.y, acc[r][0]); UNPK2(o.z, o.w, acc[r][1]);
                ((float4*)(sH3 + (4 * warp + r) * 132))[lane] = relu4(o);
            }
        }
        __syncthreads();

        // GEMM2: OUT = H3 @ W4 + b4 (70 cols, padded to 96)
        {
            float a0[4], a1[4], a2[4];
            float b40 = sb4[lane], b41 = sb4[32 + lane], b42 = sb4[64 + lane];
#pragma unroll
            for (int r = 0; r < 4; r++) { a0[r] = b40; a1[r] = b41; a2[r] = b42; }
#pragma unroll 4
            for (int k = 0; k < 128; k++) {
                const float* wr = sW4 + k * 96;
                float w0 = wr[lane], w1 = wr[32 + lane], w2 = wr[64 + lane];
#pragma unroll
                for (int r = 0; r < 4; r++) {
                    float h = sH3[(4 * warp + r) * 132 + k];
                    a0[r] = fmaf(h, w0, a0[r]);
                    a1[r] = fmaf(h, w1, a1[r]);
                    a2[r] = fmaf(h, w2, a2[r]);
                }
            }
#pragma unroll
            for (int r = 0; r < 4; r++) {
                float* orow = sO + (4 * warp + r) * 72;
                orow[lane] = a0[r];
                orow[32 + lane] = a1[r];
                if (lane < 6) orow[64 + lane] = a2[r];
            }
        }
        __syncthreads();

        // epilogue: xfeat_out = xfeat + xupd
        for (int idx = tid; idx < 2048; idx += 256) {
            int n = idx >> 6, c = idx & 63;
            int gn = nb + n;
            out[(size_t)gn * 77 + c] = xfeat[(size_t)gn * 64 + c] + sO[n * 72 + c];
        }
        // SE3 exp + compose, one thread per node
        if (tid < 32) {
            const int n = tid, gn = nb + n;
            const float* orow = sO + n * 72;
            float rho0 = orow[64], rho1 = orow[65], rho2 = orow[66];
            float p0 = orow[67], p1 = orow[68], p2 = orow[69];
            float th0 = sqrtf(p0 * p0 + p1 * p1 + p2 * p2);
            float s = PI_F * tanhf(th0 / PI_F) / (th0 + 1e-8f);
            p0 *= s; p1 *= s; p2 *= s;
            float th2 = p0 * p0 + p1 * p1 + p2 * p2;
            float th = sqrtf(th2 + 1e-12f);
            float a, b, c;
            if (th < 1e-4f) {
                a = 1.f - th2 / 6.f;
                b = 0.5f - th2 / 24.f;
                c = 1.f / 6.f - th2 / 120.f;
            } else {
                float sth = sinf(th), cth = cosf(th);
                a = sth / th;
                b = (1.f - cth) / th2;
                c = (th - sth) / (th2 * th);
            }
            float R[9], V[9];
            R[0] = 1.f + b * (p0 * p0 - th2); R[1] = -a * p2 + b * p0 * p1; R[2] =  a * p1 + b * p0 * p2;
            R[3] =  a * p2 + b * p1 * p0;    R[4] = 1.f + b * (p1 * p1 - th2); R[5] = -a * p0 + b * p1 * p2;
            R[6] = -a * p1 + b * p2 * p0;    R[7] =  a * p0 + b * p2 * p1; R[8] = 1.f + b * (p2 * p2 - th2);
            V[0] = 1.f + c * (p0 * p0 - th2); V[1] = -b * p2 + c * p0 * p1; V[2] =  b * p1 + c * p0 * p2;
            V[3] =  b * p2 + c * p1 * p0;    V[4] = 1.f + c * (p1 * p1 - th2); V[5] = -b * p0 + c * p1 * p2;
            V[6] = -b * p1 + c * p2 * p0;    V[7] =  b * p0 + c * p2 * p1; V[8] = 1.f + c * (p2 * p2 - th2);
            float td0 = V[0] * rho0 + V[1] * rho1 + V[2] * rho2;
            float td1 = V[3] * rho0 + V[4] * rho1 + V[5] * rho2;
            float td2 = V[6] * rho0 + V[7] * rho1 + V[8] * rho2;

            float TRn[9], Ttn[3];
#pragma unroll
            for (int k = 0; k < 9; k++) TRn[k] = T_R[(size_t)gn * 9 + k];
#pragma unroll
            for (int k = 0; k < 3; k++) Ttn[k] = T_t[(size_t)gn * 3 + k];

            float* op = out + (size_t)gn * 77 + 64;
#pragma unroll
            for (int r = 0; r < 3; r++) {
#pragma unroll
                for (int cc = 0; cc < 3; cc++)
                    op[3 * r + cc] = R[r * 3 + 0] * TRn[0 * 3 + cc]
                                   + R[r * 3 + 1] * TRn[1 * 3 + cc]
                                   + R[r * 3 + 2] * TRn[2 * 3 + cc];
            }
            float tdv[3] = {td0, td1, td2};
#pragma unroll
            for (int r = 0; r < 3; r++)
                op[9 + r] = R[r * 3 + 0] * Ttn[0] + R[r * 3 + 1] * Ttn[1]
                          + R[r * 3 + 2] * Ttn[2] + tdv[r];
            op[12] = sqrtf(th2);
        }
    }
}

// ---------------------------------------------------------------------------
// Host launcher
// ---------------------------------------------------------------------------
extern "C" void kernel_launch(void* const* d_in, const int* in_sizes, int n_in,
                              void* d_out, int out_size) {
    (void)in_sizes; (void)n_in; (void)out_size;
    const float* xfeat     = (const float*)d_in[0];
    const float* T_R       = (const float*)d_in[1];
    const float* T_t       = (const float*)d_in[2];
    const float* edge_feat = (const float*)d_in[3];
    const float* Tij_R     = (const float*)d_in[4];
    const float* Tij_t     = (const float*)d_in[5];
    const float* u         = (const float*)d_in[6];
    const int*   edge_idx  = (const int*)d_in[7];
    const int*   batch     = (const int*)d_in[8];
    const float* W1 = (const float*)d_in[9];
    const float* b1 = (const float*)d_in[10];
    const float* W2 = (const float*)d_in[11];
    const float* b2 = (const float*)d_in[12];
    const float* W3 = (const float*)d_in[13];
    const float* b3 = (const float*)d_in[14];
    const float* W4 = (const float*)d_in[15];
    const float* b4 = (const float*)d_in[16];
    float* out = (float*)d_out;

    cudaFuncSetAttribute(k_pre,  cudaFuncAttributeMaxDynamicSharedMemorySize, PRE_SMEM);
    cudaFuncSetAttribute(k_edge, cudaFuncAttributeMaxDynamicSharedMemorySize, EDGE_SMEM);
    cudaFuncSetAttribute(k_node, cudaFuncAttributeMaxDynamicSharedMemorySize, NODE_SMEM);

    k_pre<<<296, 256, PRE_SMEM>>>(xfeat, W1);
    k_edge<<<148, 640, EDGE_SMEM>>>(T_R, T_t, edge_feat, Tij_R, Tij_t,
                                    edge_idx, W1, b1, W2, b2);
    k_node<<<148, 256, NODE_SMEM>>>(xfeat, T_R, T_t, u, batch,
                                    W3, b3, W4, b4, out);
}